// round 1
// baseline (speedup 1.0000x reference)
#include <cuda_runtime.h>
#include <stdint.h>

#define N_LEVELS 6
#define HASHMAP_SIZE (1u << 19)
#define HASH_MASK (HASHMAP_SIZE - 1u)
#define SPHERE_R 500.0f

// per-level scale = 16*2^L - 1 (PER_LEVEL_SCALE is exactly 2.0 in double)
__device__ __constant__ float d_scales[N_LEVELS] = {15.f, 31.f, 63.f, 127.f, 255.f, 511.f};
// res = scale + 1; levels 0..2 dense (res^3 <= 2^19), 3..5 hashed

__global__ void __launch_bounds__(256)
sphere_hashgrid_kernel(const float* __restrict__ dirs,
                       const float* __restrict__ origs,
                       const float* __restrict__ table,
                       float4* __restrict__ out,
                       int n)
{
    int i = blockIdx.x * blockDim.x + threadIdx.x;
    if (i >= n) return;

    // --- ray-sphere intersection ---
    const float dx = dirs[3 * i + 0], dy = dirs[3 * i + 1], dz = dirs[3 * i + 2];
    const float ox = origs[3 * i + 0], oy = origs[3 * i + 1], oz = origs[3 * i + 2];

    float b    = 2.0f * (ox * dx + oy * dy + oz * dz);
    float c    = (ox * ox + oy * oy + oz * oz) - SPHERE_R * SPHERE_R;
    float disc = b * b - 4.0f * c;
    float t    = 0.5f * (sqrtf(fmaxf(disc, 0.0f)) - b);

    const float inv2R = 1.0f / (2.0f * SPHERE_R);
    float cx = fminf(fmaxf((ox + t * dx + SPHERE_R) * inv2R, 0.0f), 1.0f);
    float cy = fminf(fmaxf((oy + t * dy + SPHERE_R) * inv2R, 0.0f), 1.0f);
    float cz = fminf(fmaxf((oz + t * dz + SPHERE_R) * inv2R, 0.0f), 1.0f);

    float4* orow = out + (size_t)i * 6;

#pragma unroll
    for (int L = 0; L < N_LEVELS; ++L) {
        const float scale = d_scales[L];
        float px = cx * scale + 0.5f;
        float py = cy * scale + 0.5f;
        float pz = cz * scale + 0.5f;
        float fx = floorf(px), fy = floorf(py), fz = floorf(pz);
        float wx = px - fx, wy = py - fy, wz = pz - fz;
        uint32_t gx = (uint32_t)fx, gy = (uint32_t)fy, gz = (uint32_t)fz;

        uint32_t i000, i100, i010, i110, i001, i101, i011, i111;
        if (L < 3) {
            // dense indexing: idx = x + y*res + z*res^2, corners clamped to res-1
            const uint32_t r  = 16u << L;
            const uint32_t rm = r - 1u;
            uint32_t x0 = min(gx, rm),        x1 = min(gx + 1u, rm);
            uint32_t y0 = min(gy, rm) * r,    y1 = min(gy + 1u, rm) * r;
            uint32_t z0 = min(gz, rm) * r * r, z1 = min(gz + 1u, rm) * r * r;
            i000 = x0 + y0 + z0; i100 = x1 + y0 + z0;
            i010 = x0 + y1 + z0; i110 = x1 + y1 + z0;
            i001 = x0 + y0 + z1; i101 = x1 + y0 + z1;
            i011 = x0 + y1 + z1; i111 = x1 + y1 + z1;
        } else {
            // spatial hash: x*1 ^ y*p1 ^ z*p2, masked to table size
            uint32_t hx0 = gx,                       hx1 = gx + 1u;
            uint32_t hy0 = gy * 2654435761u,         hy1 = (gy + 1u) * 2654435761u;
            uint32_t hz0 = gz * 805459861u,          hz1 = (gz + 1u) * 805459861u;
            i000 = (hx0 ^ hy0 ^ hz0) & HASH_MASK; i100 = (hx1 ^ hy0 ^ hz0) & HASH_MASK;
            i010 = (hx0 ^ hy1 ^ hz0) & HASH_MASK; i110 = (hx1 ^ hy1 ^ hz0) & HASH_MASK;
            i001 = (hx0 ^ hy0 ^ hz1) & HASH_MASK; i101 = (hx1 ^ hy0 ^ hz1) & HASH_MASK;
            i011 = (hx0 ^ hy1 ^ hz1) & HASH_MASK; i111 = (hx1 ^ hy1 ^ hz1) & HASH_MASK;
        }

        const float4* tab = reinterpret_cast<const float4*>(table) + (size_t)L * HASHMAP_SIZE;
        // issue all 8 gathers back-to-back (MLP=8)
        float4 f000 = __ldg(tab + i000);
        float4 f100 = __ldg(tab + i100);
        float4 f010 = __ldg(tab + i010);
        float4 f110 = __ldg(tab + i110);
        float4 f001 = __ldg(tab + i001);
        float4 f101 = __ldg(tab + i101);
        float4 f011 = __ldg(tab + i011);
        float4 f111 = __ldg(tab + i111);

        float ux = 1.0f - wx, uy = 1.0f - wy, uz = 1.0f - wz;
        float w000 = ux * uy * uz, w100 = wx * uy * uz;
        float w010 = ux * wy * uz, w110 = wx * wy * uz;
        float w001 = ux * uy * wz, w101 = wx * uy * wz;
        float w011 = ux * wy * wz, w111 = wx * wy * wz;

        float4 acc;
        acc.x = f000.x * w000 + f100.x * w100 + f010.x * w010 + f110.x * w110
              + f001.x * w001 + f101.x * w101 + f011.x * w011 + f111.x * w111;
        acc.y = f000.y * w000 + f100.y * w100 + f010.y * w010 + f110.y * w110
              + f001.y * w001 + f101.y * w101 + f011.y * w011 + f111.y * w111;
        acc.z = f000.z * w000 + f100.z * w100 + f010.z * w010 + f110.z * w110
              + f001.z * w001 + f101.z * w101 + f011.z * w011 + f111.z * w111;
        acc.w = f000.w * w000 + f100.w * w100 + f010.w * w010 + f110.w * w110
              + f001.w * w001 + f101.w * w101 + f011.w * w011 + f111.w * w111;

        orow[L] = acc;
    }
}

extern "C" void kernel_launch(void* const* d_in, const int* in_sizes, int n_in,
                              void* d_out, int out_size)
{
    const float* view_dirs   = (const float*)d_in[0];
    const float* ray_origins = (const float*)d_in[1];
    const float* table       = (const float*)d_in[2];
    float4* out              = (float4*)d_out;

    int n = in_sizes[0] / 3;  // N_RAYS
    int threads = 256;
    int blocks = (n + threads - 1) / threads;
    sphere_hashgrid_kernel<<<blocks, threads>>>(view_dirs, ray_origins, table, out, n);
}